// round 1
// baseline (speedup 1.0000x reference)
#include <cuda_runtime.h>
#include <math.h>
#include <stdint.h>

#define TOK   16384      // B*T
#define Dm    512
#define Tt    4096
#define Bb    4
#define Hh    8
#define HDm   64
#define Lnum  6
#define MLPD  2048

// ---- scratch (device globals; no allocation allowed) ----
__device__ float g_x[TOK * Dm];
__device__ float g_h[TOK * Dm];
__device__ float g_q[TOK * Dm];
__device__ float g_k[TOK * Dm];
__device__ float g_v[TOK * Dm];
__device__ float g_attn[TOK * Dm];
__device__ float g_mlp[(size_t)TOK * MLPD];

// ============================================================
// Embedding + sinusoidal PE (replicates numpy fp32 pipeline)
// ============================================================
__global__ void embed_kernel(const int* __restrict__ inputs,
                             const float* __restrict__ embed,
                             float* __restrict__ x) {
    size_t id = (size_t)blockIdx.x * blockDim.x + threadIdx.x;  // over TOK*Dm
    int token = (int)(id >> 9);          // /512
    int d     = (int)(id & 511);
    int pos   = token & (Tt - 1);        // position within sequence
    int tok   = inputs[token];

    int i = (d < 256) ? d : d - 256;
    // numpy: div = exp(f32(2i) * f32(-log(10000)/512))
    const float c = (float)(-9.210340371976184 / 512.0);  // -log(10000)/512
    float div = expf((float)(2 * i) * c);
    float ang = (float)pos * div;
    float pe  = (d < 256) ? sinf(ang) : cosf(ang);

    x[id] = embed[(size_t)tok * Dm + d] + pe;
}

// ============================================================
// LayerNorm: one block (128 thr) per token, D=512
// ============================================================
__global__ void ln_kernel(const float* __restrict__ x,
                          const float* __restrict__ sc,
                          const float* __restrict__ bi,
                          float* __restrict__ out) {
    __shared__ float red[4];
    int t = blockIdx.x;
    const float* xr = x + (size_t)t * Dm;

    float v[4];
    float sum = 0.f;
#pragma unroll
    for (int i = 0; i < 4; i++) {
        v[i] = xr[threadIdx.x + i * 128];
        sum += v[i];
    }
#pragma unroll
    for (int o = 16; o; o >>= 1) sum += __shfl_xor_sync(0xffffffffu, sum, o);
    if ((threadIdx.x & 31) == 0) red[threadIdx.x >> 5] = sum;
    __syncthreads();
    float mean = (red[0] + red[1] + red[2] + red[3]) * (1.f / Dm);
    __syncthreads();

    float sq = 0.f;
#pragma unroll
    for (int i = 0; i < 4; i++) {
        float d = v[i] - mean;
        sq += d * d;
    }
#pragma unroll
    for (int o = 16; o; o >>= 1) sq += __shfl_xor_sync(0xffffffffu, sq, o);
    if ((threadIdx.x & 31) == 0) red[threadIdx.x >> 5] = sq;
    __syncthreads();
    float var = (red[0] + red[1] + red[2] + red[3]) * (1.f / Dm);
    float rstd = rsqrtf(var + 1e-6f);

#pragma unroll
    for (int i = 0; i < 4; i++) {
        int idx = threadIdx.x + i * 128;
        out[(size_t)t * Dm + idx] = (v[i] - mean) * rstd * sc[idx] + bi[idx];
    }
}

// ============================================================
// Tiled fp32 GEMM: C[M,N] (+)= A[M,K] @ B[K,N] (+bias)(relu)
// BM=BN=64, BK=32, 256 threads, 4x4 per thread.
// M%64==0, N%64==0, K%32==0 guaranteed by problem shapes.
// ============================================================
template <bool RELU, bool ACCUM>
__global__ void gemm_kernel(const float* __restrict__ A,
                            const float* __restrict__ B,
                            const float* __restrict__ bias,
                            float* __restrict__ C,
                            int M, int N, int K) {
    __shared__ float As[32][64];
    __shared__ float Bs[32][64];

    int tid = threadIdx.x;
    int tx = tid & 15, ty = tid >> 4;
    int bm = blockIdx.y * 64, bn = blockIdx.x * 64;

    float acc[4][4] = {};

    for (int kt = 0; kt < K; kt += 32) {
#pragma unroll
        for (int i = 0; i < 2; i++) {
            int t4 = tid + i * 256;
            // A tile: 64 rows x 8 float4 (transpose into As[k][m])
            int row = t4 >> 3, c4 = t4 & 7;
            float4 av = *(const float4*)(A + (size_t)(bm + row) * K + kt + c4 * 4);
            As[c4 * 4 + 0][row] = av.x;
            As[c4 * 4 + 1][row] = av.y;
            As[c4 * 4 + 2][row] = av.z;
            As[c4 * 4 + 3][row] = av.w;
            // B tile: 32 rows x 16 float4 (direct)
            int rowb = t4 >> 4, c4b = t4 & 15;
            *(float4*)(&Bs[rowb][c4b * 4]) =
                *(const float4*)(B + (size_t)(kt + rowb) * N + bn + c4b * 4);
        }
        __syncthreads();

#pragma unroll
        for (int kk = 0; kk < 32; kk++) {
            float4 a = *(float4*)(&As[kk][ty * 4]);
            float4 b = *(float4*)(&Bs[kk][tx * 4]);
            float av[4] = {a.x, a.y, a.z, a.w};
            float bv[4] = {b.x, b.y, b.z, b.w};
#pragma unroll
            for (int i = 0; i < 4; i++)
#pragma unroll
                for (int j = 0; j < 4; j++)
                    acc[i][j] += av[i] * bv[j];
        }
        __syncthreads();
    }

    float bb[4] = {0.f, 0.f, 0.f, 0.f};
    if (bias) {
        float4 bv = *(const float4*)(bias + bn + tx * 4);
        bb[0] = bv.x; bb[1] = bv.y; bb[2] = bv.z; bb[3] = bv.w;
    }
#pragma unroll
    for (int i = 0; i < 4; i++) {
        float r[4];
#pragma unroll
        for (int j = 0; j < 4; j++) {
            r[j] = acc[i][j] + bb[j];
            if (RELU) r[j] = fmaxf(r[j], 0.f);
        }
        float4* cp = (float4*)(C + (size_t)(bm + ty * 4 + i) * N + bn + tx * 4);
        if (ACCUM) {
            float4 old = *cp;
            r[0] += old.x; r[1] += old.y; r[2] += old.z; r[3] += old.w;
        }
        *cp = make_float4(r[0], r[1], r[2], r[3]);
    }
}

// ============================================================
// Local block attention: one CTA per (block n, head h, batch b)
// 256 threads. buf0: Q then S/P; buf1: K then V. masks separate.
// ============================================================
__global__ void attn_kernel(const float* __restrict__ q,
                            const float* __restrict__ k,
                            const float* __restrict__ v,
                            const int* __restrict__ inputs,
                            float* __restrict__ attn,
                            int lp) {
    __shared__ float buf0[64 * 64];
    __shared__ float buf1[64 * 64];
    __shared__ float maskS[64];

    int n = blockIdx.x, h = blockIdx.y, b = blockIdx.z;
    int tid = threadIdx.x;
    int base = n * 64 - lp;  // global token of row 0

    // Load Q -> buf0, K -> buf1
#pragma unroll
    for (int i = 0; i < 4; i++) {
        int t4 = tid + i * 256;
        int row = t4 >> 4, c4 = t4 & 15;
        int gt = base + row;
        float4 qv = make_float4(0.f, 0.f, 0.f, 0.f);
        float4 kv = qv;
        if (gt >= 0 && gt < Tt) {
            size_t off = ((size_t)(b * Tt + gt)) * Dm + h * HDm;
            qv = ((const float4*)(q + off))[c4];
            kv = ((const float4*)(k + off))[c4];
        }
        ((float4*)(buf0 + row * 64))[c4] = qv;
        ((float4*)(buf1 + row * 64))[c4] = kv;
    }
    if (tid < 64) {
        int gt = base + tid;
        maskS[tid] = (gt >= 0 && gt < Tt && inputs[b * Tt + gt] > 0) ? 1.f : 0.f;
    }
    __syncthreads();

    // Scores: thread -> row qr, cols kc0..kc0+15
    int qr = tid >> 2;
    int kc0 = (tid & 3) * 16;
    float acc[16];
#pragma unroll
    for (int j = 0; j < 16; j++) acc[j] = 0.f;
#pragma unroll
    for (int f4 = 0; f4 < 16; f4++) {
        float4 qv = ((float4*)(buf0 + qr * 64))[f4];
#pragma unroll
        for (int j = 0; j < 16; j++) {
            float4 kv = ((float4*)(buf1 + (kc0 + j) * 64))[f4];
            acc[j] += qv.x * kv.x + qv.y * kv.y + qv.z * kv.z + qv.w * kv.w;
        }
    }
    __syncthreads();  // done reading Q/K

    // Write S (scale + mask) into buf0; load V into buf1
#pragma unroll
    for (int j = 0; j < 16; j++)
        buf0[qr * 64 + kc0 + j] =
            (maskS[kc0 + j] > 0.f) ? acc[j] * 0.125f : -1e9f;

#pragma unroll
    for (int i = 0; i < 4; i++) {
        int t4 = tid + i * 256;
        int row = t4 >> 4, c4 = t4 & 15;
        int gt = base + row;
        float4 vv = make_float4(0.f, 0.f, 0.f, 0.f);
        if (gt >= 0 && gt < Tt)
            vv = ((const float4*)(v + ((size_t)(b * Tt + gt)) * Dm + h * HDm))[c4];
        ((float4*)(buf1 + row * 64))[c4] = vv;
    }
    __syncthreads();

    // Softmax per row (64 threads)
    if (tid < 64) {
        float* row = buf0 + tid * 64;
        float m = -1e30f;
#pragma unroll 8
        for (int i2 = 0; i2 < 64; i2++) m = fmaxf(m, row[i2]);
        float s = 0.f;
#pragma unroll 8
        for (int i2 = 0; i2 < 64; i2++) {
            float e = expf(row[i2] - m);
            row[i2] = e;
            s += e;
        }
        float inv = 1.f / s;
#pragma unroll 8
        for (int i2 = 0; i2 < 64; i2++) row[i2] *= inv;
    }
    __syncthreads();

    // O = P @ V: thread -> row qr, features kc0..kc0+15
    float o[16];
#pragma unroll
    for (int j = 0; j < 16; j++) o[j] = 0.f;
    for (int kk = 0; kk < 64; kk++) {
        float p = buf0[qr * 64 + kk];
#pragma unroll
        for (int j4 = 0; j4 < 4; j4++) {
            float4 vv = ((float4*)(buf1 + kk * 64 + kc0))[j4];
            o[j4 * 4 + 0] += p * vv.x;
            o[j4 * 4 + 1] += p * vv.y;
            o[j4 * 4 + 2] += p * vv.z;
            o[j4 * 4 + 3] += p * vv.w;
        }
    }
    int gt = base + qr;
    if (gt >= 0 && gt < Tt) {
        float* dst = attn + ((size_t)(b * Tt + gt)) * Dm + h * HDm + kc0;
#pragma unroll
        for (int j4 = 0; j4 < 4; j4++)
            ((float4*)dst)[j4] =
                make_float4(o[j4 * 4 + 0], o[j4 * 4 + 1], o[j4 * 4 + 2], o[j4 * 4 + 3]);
    }
}

// ============================================================
// Host driver
// ============================================================
extern "C" void kernel_launch(void* const* d_in, const int* in_sizes, int n_in,
                              void* d_out, int out_size) {
    const int*   inputs = (const int*)  d_in[0];
    const float* embed  = (const float*)d_in[1];
    const float* wq     = (const float*)d_in[2];
    const float* wk     = (const float*)d_in[3];
    const float* wv     = (const float*)d_in[4];
    const float* wo     = (const float*)d_in[5];
    const float* ln1_s  = (const float*)d_in[6];
    const float* ln1_b  = (const float*)d_in[7];
    const float* ln2_s  = (const float*)d_in[8];
    const float* ln2_b  = (const float*)d_in[9];
    const float* w1     = (const float*)d_in[10];
    const float* b1     = (const float*)d_in[11];
    const float* w2     = (const float*)d_in[12];
    const float* b2     = (const float*)d_in[13];
    const float* lnf_s  = (const float*)d_in[14];
    const float* lnf_b  = (const float*)d_in[15];

    float *x, *h, *q, *k, *v, *attn, *mlp;
    cudaGetSymbolAddress((void**)&x,    g_x);
    cudaGetSymbolAddress((void**)&h,    g_h);
    cudaGetSymbolAddress((void**)&q,    g_q);
    cudaGetSymbolAddress((void**)&k,    g_k);
    cudaGetSymbolAddress((void**)&v,    g_v);
    cudaGetSymbolAddress((void**)&attn, g_attn);
    cudaGetSymbolAddress((void**)&mlp,  g_mlp);

    embed_kernel<<<(TOK * Dm) / 256, 256>>>(inputs, embed, x);

    dim3 gP(Dm / 64, TOK / 64);      // 512-wide GEMMs
    dim3 gM1(MLPD / 64, TOK / 64);   // MLP up-proj

    for (int l = 0; l < Lnum; l++) {
        int lp = (l & 1) ? 32 : 0;
        int nb = (l & 1) ? (Tt + 64) / 64 : Tt / 64;

        ln_kernel<<<TOK, 128>>>(x, ln1_s + l * Dm, ln1_b + l * Dm, h);

        const float* wql = wq + (size_t)l * Dm * Dm;
        const float* wkl = wk + (size_t)l * Dm * Dm;
        const float* wvl = wv + (size_t)l * Dm * Dm;
        const float* wol = wo + (size_t)l * Dm * Dm;
        gemm_kernel<false, false><<<gP, 256>>>(h, wql, nullptr, q, TOK, Dm, Dm);
        gemm_kernel<false, false><<<gP, 256>>>(h, wkl, nullptr, k, TOK, Dm, Dm);
        gemm_kernel<false, false><<<gP, 256>>>(h, wvl, nullptr, v, TOK, Dm, Dm);

        attn_kernel<<<dim3(nb, Hh, Bb), 256>>>(q, k, v, inputs, attn, lp);

        // x += attn @ wo
        gemm_kernel<false, true><<<gP, 256>>>(attn, wol, nullptr, x, TOK, Dm, Dm);

        ln_kernel<<<TOK, 128>>>(x, ln2_s + l * Dm, ln2_b + l * Dm, h);

        // mlp = relu(h @ w1 + b1)
        gemm_kernel<true, false><<<gM1, 256>>>(h, w1 + (size_t)l * Dm * MLPD,
                                               b1 + (size_t)l * MLPD, mlp,
                                               TOK, MLPD, Dm);
        // x += mlp @ w2 + b2
        gemm_kernel<false, true><<<gP, 256>>>(mlp, w2 + (size_t)l * MLPD * Dm,
                                              b2 + (size_t)l * Dm, x,
                                              TOK, Dm, MLPD);
    }

    ln_kernel<<<TOK, 128>>>(x, lnf_s, lnf_b, (float*)d_out);
}

// round 3
// speedup vs baseline: 2.3298x; 2.3298x over previous
#include <cuda_runtime.h>
#include <cuda_bf16.h>
#include <math.h>
#include <stdint.h>

#define TOK   16384
#define Dm    512
#define Tt    4096
#define Bb    4
#define Hh    8
#define HDm   64
#define Lnum  6
#define MLPD  2048

#define WSZP  (Dm*Dm)
#define WSZM  (Dm*MLPD)
#define OFF_WQ 0
#define OFF_WK (6*WSZP)
#define OFF_WV (12*WSZP)
#define OFF_WO (18*WSZP)
#define OFF_W1 (24*WSZP)
#define OFF_W2 (OFF_W1 + 6*WSZM)
#define WTOT   (OFF_W2 + 6*WSZM)

// ---------------- scratch (device globals) ----------------
__device__ __align__(128) float g_x[TOK * Dm];
__device__ __align__(128) float g_q[TOK * Dm];
__device__ __align__(128) float g_k[TOK * Dm];
__device__ __align__(128) float g_v[TOK * Dm];
__device__ __align__(128) __nv_bfloat16 g_hhi[TOK * Dm];
__device__ __align__(128) __nv_bfloat16 g_hlo[TOK * Dm];
__device__ __align__(128) __nv_bfloat16 g_ahi[TOK * Dm];
__device__ __align__(128) __nv_bfloat16 g_alo[TOK * Dm];
__device__ __align__(128) __nv_bfloat16 g_mhi[(size_t)TOK * MLPD];
__device__ __align__(128) __nv_bfloat16 g_mlo[(size_t)TOK * MLPD];
__device__ __align__(128) __nv_bfloat16 g_whi[WTOT];
__device__ __align__(128) __nv_bfloat16 g_wlo[WTOT];

// ---------------- helpers ----------------
__device__ __forceinline__ uint32_t smem_u32(const void* p) {
    uint32_t a;
    asm("{ .reg .u64 t; cvta.to.shared.u64 t, %1; cvt.u32.u64 %0, t; }" : "=r"(a) : "l"(p));
    return a;
}
#define SWZ(o) ((o) ^ (((o) >> 3) & 0x70))

#define CP16(dst, src) \
    asm volatile("cp.async.cg.shared.global [%0], [%1], 16;" :: "r"(dst), "l"(src) : "memory")
#define CP_COMMIT() asm volatile("cp.async.commit_group;" ::: "memory")
#define CP_WAIT(n)  asm volatile("cp.async.wait_group %0;" :: "n"(n) : "memory")

__device__ __forceinline__ void ldsm4(uint32_t* r, uint32_t a) {
    asm volatile("ldmatrix.sync.aligned.m8n8.x4.shared.b16 {%0,%1,%2,%3}, [%4];"
                 : "=r"(r[0]), "=r"(r[1]), "=r"(r[2]), "=r"(r[3]) : "r"(a));
}
__device__ __forceinline__ void mma16816(float* c, const uint32_t* a,
                                         uint32_t b0, uint32_t b1) {
    asm volatile("mma.sync.aligned.m16n8k16.row.col.f32.bf16.bf16.f32 "
                 "{%0,%1,%2,%3},{%4,%5,%6,%7},{%8,%9},{%0,%1,%2,%3};"
                 : "+f"(c[0]), "+f"(c[1]), "+f"(c[2]), "+f"(c[3])
                 : "r"(a[0]), "r"(a[1]), "r"(a[2]), "r"(a[3]), "r"(b0), "r"(b1));
}
__device__ __forceinline__ void bfsplit(float x, __nv_bfloat16& h, __nv_bfloat16& l) {
    h = __float2bfloat16(x);
    l = __float2bfloat16(x - __bfloat162float(h));
}

// ============================================================
// Embedding + PE
// ============================================================
__global__ void embed_kernel(const int* __restrict__ inputs,
                             const float* __restrict__ embed,
                             float* __restrict__ x) {
    size_t id = (size_t)blockIdx.x * blockDim.x + threadIdx.x;
    int token = (int)(id >> 9);
    int d = (int)(id & 511);
    int pos = token & (Tt - 1);
    int tok = inputs[token];
    int i = (d < 256) ? d : d - 256;
    const float c = (float)(-9.210340371976184 / 512.0);
    float div = expf((float)(2 * i) * c);
    float ang = (float)pos * div;
    float pe = (d < 256) ? sinf(ang) : cosf(ang);
    x[id] = embed[(size_t)tok * Dm + d] + pe;
}

// ============================================================
// Weight prep: transpose [K][N] fp32 -> [N][K] bf16 hi/lo
// ============================================================
__global__ void wprep(const float* __restrict__ W, __nv_bfloat16* __restrict__ hi,
                      __nv_bfloat16* __restrict__ lo, int K, int N) {
    __shared__ float t[32][33];
    int l = blockIdx.z;
    const float* Wl = W + (size_t)l * K * N;
    __nv_bfloat16* Hl = hi + (size_t)l * K * N;
    __nv_bfloat16* Ll = lo + (size_t)l * K * N;
    int n0 = blockIdx.x * 32, k0 = blockIdx.y * 32;
    int tx = threadIdx.x, ty = threadIdx.y;
#pragma unroll
    for (int i = 0; i < 4; i++)
        t[ty + i * 8][tx] = Wl[(size_t)(k0 + ty + i * 8) * N + n0 + tx];
    __syncthreads();
#pragma unroll
    for (int i = 0; i < 4; i++) {
        float v = t[tx][ty + i * 8];
        __nv_bfloat16 h, L;
        bfsplit(v, h, L);
        size_t o = (size_t)(n0 + ty + i * 8) * K + k0 + tx;
        Hl[o] = h;
        Ll[o] = L;
    }
}

// ============================================================
// LayerNorm
// ============================================================
template <bool WBF>
__global__ void ln_kernel(const float* __restrict__ x,
                          const float* __restrict__ sc,
                          const float* __restrict__ bi,
                          float* __restrict__ outf,
                          __nv_bfloat16* __restrict__ ohi,
                          __nv_bfloat16* __restrict__ olo) {
    __shared__ float red[4];
    int t = blockIdx.x;
    const float* xr = x + (size_t)t * Dm;
    float v[4];
    float sum = 0.f;
#pragma unroll
    for (int i = 0; i < 4; i++) { v[i] = xr[threadIdx.x + i * 128]; sum += v[i]; }
#pragma unroll
    for (int o = 16; o; o >>= 1) sum += __shfl_xor_sync(0xffffffffu, sum, o);
    if ((threadIdx.x & 31) == 0) red[threadIdx.x >> 5] = sum;
    __syncthreads();
    float mean = (red[0] + red[1] + red[2] + red[3]) * (1.f / Dm);
    __syncthreads();
    float sq = 0.f;
#pragma unroll
    for (int i = 0; i < 4; i++) { float d = v[i] - mean; sq += d * d; }
#pragma unroll
    for (int o = 16; o; o >>= 1) sq += __shfl_xor_sync(0xffffffffu, sq, o);
    if ((threadIdx.x & 31) == 0) red[threadIdx.x >> 5] = sq;
    __syncthreads();
    float var = (red[0] + red[1] + red[2] + red[3]) * (1.f / Dm);
    float rstd = rsqrtf(var + 1e-6f);
#pragma unroll
    for (int i = 0; i < 4; i++) {
        int idx = threadIdx.x + i * 128;
        float y = (v[i] - mean) * rstd * sc[idx] + bi[idx];
        if (WBF) {
            __nv_bfloat16 h, L;
            bfsplit(y, h, L);
            ohi[(size_t)t * Dm + idx] = h;
            olo[(size_t)t * Dm + idx] = L;
        } else {
            outf[(size_t)t * Dm + idx] = y;
        }
    }
}

// ============================================================
// HMMA bf16 split-precision GEMM
// C[M,N] (+)= (Ahi+Alo)[M,K] @ (Bhi+Blo)[N,K]^T  (drop lo*lo)
// Tile 128x128, K-chunk 64, cp.async 2-stage, 256 threads.
// ============================================================
#define ST_A_HI 0
#define ST_A_LO 16384
#define ST_B_HI 32768
#define ST_B_LO 49152
#define STAGE   65536
#define SMEM_GEMM (2 * STAGE)

template <bool ACCUM, bool RELU, bool BIAS, bool WF32, bool WBF>
__global__ void __launch_bounds__(256, 1)
hgemm(const __nv_bfloat16* __restrict__ Ahi, const __nv_bfloat16* __restrict__ Alo,
      const __nv_bfloat16* __restrict__ Bhi, const __nv_bfloat16* __restrict__ Blo,
      const float* __restrict__ bias, float* __restrict__ C,
      __nv_bfloat16* __restrict__ Ohi, __nv_bfloat16* __restrict__ Olo,
      int N, int K) {
    extern __shared__ char smem[];
    uint32_t sb = smem_u32(smem);
    int tid = threadIdx.x, wid = tid >> 5, lane = tid & 31;
    int m0 = blockIdx.y * 128, n0 = blockIdx.x * 128;
    int wm = (wid >> 1) * 32, wn = (wid & 1) * 64;

    float acc[2][8][4];
#pragma unroll
    for (int i = 0; i < 2; i++)
#pragma unroll
        for (int j = 0; j < 8; j++)
#pragma unroll
            for (int e = 0; e < 4; e++) acc[i][j][e] = 0.f;

    const int NC = K >> 6;

#define LOAD_CHUNK(c, s) do {                                                   \
    int kt = (c) << 6;                                                          \
    uint32_t st = sb + (s) * STAGE;                                             \
    _Pragma("unroll")                                                           \
    for (int i = 0; i < 4; i++) {                                               \
        int u = tid + i * 256;                                                  \
        int row = u >> 3, kc = u & 7;                                           \
        uint32_t so = SWZ((uint32_t)(row * 128 + kc * 16));                     \
        size_t ga = (size_t)(m0 + row) * K + kt + kc * 8;                       \
        size_t gb = (size_t)(n0 + row) * K + kt + kc * 8;                       \
        CP16(st + ST_A_HI + so, Ahi + ga);                                      \
        CP16(st + ST_A_LO + so, Alo + ga);                                      \
        CP16(st + ST_B_HI + so, Bhi + gb);                                      \
        CP16(st + ST_B_LO + so, Blo + gb);                                      \
    } } while (0)

    LOAD_CHUNK(0, 0);
    CP_COMMIT();

    for (int c = 0; c < NC; c++) {
        if (c + 1 < NC) {
            LOAD_CHUNK(c + 1, (c + 1) & 1);
            CP_COMMIT();
            CP_WAIT(1);
        } else {
            CP_WAIT(0);
        }
        __syncthreads();
        uint32_t st = sb + (c & 1) * STAGE;

#pragma unroll
        for (int ks = 0; ks < 4; ks++) {
            int kb = ks * 32 + ((lane >> 4) & 1) * 16;  // k byte offset in row
            uint32_t ah[2][4], al[2][4], bh[4][4], bl[4][4];
#pragma unroll
            for (int mf = 0; mf < 2; mf++) {
                uint32_t ro = (uint32_t)((wm + mf * 16 + (lane & 15)) * 128 + kb);
                ldsm4(ah[mf], st + ST_A_HI + SWZ(ro));
                ldsm4(al[mf], st + ST_A_LO + SWZ(ro));
            }
#pragma unroll
            for (int nf = 0; nf < 4; nf++) {
                uint32_t ro = (uint32_t)((wn + nf * 16 + (lane & 15)) * 128 + kb);
                ldsm4(bh[nf], st + ST_B_HI + SWZ(ro));
                ldsm4(bl[nf], st + ST_B_LO + SWZ(ro));
            }
#pragma unroll
            for (int mf = 0; mf < 2; mf++)
#pragma unroll
                for (int nb = 0; nb < 8; nb++) {
                    int nf = nb >> 1, sl = nb & 1;
                    mma16816(acc[mf][nb], ah[mf], bh[nf][sl], bh[nf][sl + 2]);
                    mma16816(acc[mf][nb], ah[mf], bl[nf][sl], bl[nf][sl + 2]);
                    mma16816(acc[mf][nb], al[mf], bh[nf][sl], bh[nf][sl + 2]);
                }
        }
        __syncthreads();
    }

    // epilogue
    int r0 = m0 + wm + (lane >> 2);
    int cb = n0 + wn + (lane & 3) * 2;
#pragma unroll
    for (int mf = 0; mf < 2; mf++)
#pragma unroll
        for (int half = 0; half < 2; half++) {
            int rr = r0 + mf * 16 + half * 8;
#pragma unroll
            for (int nb = 0; nb < 8; nb++) {
                int cc = cb + nb * 8;
                float v0 = acc[mf][nb][half * 2 + 0];
                float v1 = acc[mf][nb][half * 2 + 1];
                if (BIAS) {
                    float2 bv = *(const float2*)(bias + cc);
                    v0 += bv.x; v1 += bv.y;
                }
                if (RELU) { v0 = fmaxf(v0, 0.f); v1 = fmaxf(v1, 0.f); }
                if (ACCUM) {
                    float2 o = *(const float2*)(C + (size_t)rr * N + cc);
                    v0 += o.x; v1 += o.y;
                }
                if (WF32)
                    *(float2*)(C + (size_t)rr * N + cc) = make_float2(v0, v1);
                if (WBF) {
                    __nv_bfloat16 h0, l0, h1, l1;
                    bfsplit(v0, h0, l0);
                    bfsplit(v1, h1, l1);
                    *(__nv_bfloat162*)(Ohi + (size_t)rr * N + cc) = __halves2bfloat162(h0, h1);
                    *(__nv_bfloat162*)(Olo + (size_t)rr * N + cc) = __halves2bfloat162(l0, l1);
                }
            }
        }
}

// ============================================================
// Local block attention (fp32 math, bf16 hi/lo output)
// ============================================================
__global__ void attn_kernel(const float* __restrict__ q,
                            const float* __restrict__ k,
                            const float* __restrict__ v,
                            const int* __restrict__ inputs,
                            __nv_bfloat16* __restrict__ ahi,
                            __nv_bfloat16* __restrict__ alo,
                            int lp) {
    __shared__ float buf0[64 * 64];
    __shared__ float buf1[64 * 64];
    __shared__ float maskS[64];

    int n = blockIdx.x, h = blockIdx.y, b = blockIdx.z;
    int tid = threadIdx.x;
    int base = n * 64 - lp;

#pragma unroll
    for (int i = 0; i < 4; i++) {
        int t4 = tid + i * 256;
        int row = t4 >> 4, c4 = t4 & 15;
        int gt = base + row;
        float4 qv = make_float4(0.f, 0.f, 0.f, 0.f);
        float4 kv = qv;
        if (gt >= 0 && gt < Tt) {
            size_t off = ((size_t)(b * Tt + gt)) * Dm + h * HDm;
            qv = ((const float4*)(q + off))[c4];
            kv = ((const float4*)(k + off))[c4];
        }
        ((float4*)(buf0 + row * 64))[c4] = qv;
        ((float4*)(buf1 + row * 64))[c4] = kv;
    }
    if (tid < 64) {
        int gt = base + tid;
        maskS[tid] = (gt >= 0 && gt < Tt && inputs[b * Tt + gt] > 0) ? 1.f : 0.f;
    }
    __syncthreads();

    int qr = tid >> 2;
    int kc0 = (tid & 3) * 16;
    float acc[16];
#pragma unroll
    for (int j = 0; j < 16; j++) acc[j] = 0.f;
#pragma unroll
    for (int f4 = 0; f4 < 16; f4++) {
        float4 qv = ((float4*)(buf0 + qr * 64))[f4];
#pragma unroll
        for (int j = 0; j < 16; j++) {
            float4 kv = ((float4*)(buf1 + (kc0 + j) * 64))[f4];
            acc[j] += qv.x * kv.x + qv.y * kv.y + qv.z * kv.z + qv.w * kv.w;
        }
    }
    __syncthreads();

#pragma unroll
    for (int j = 0; j < 16; j++)
        buf0[qr * 64 + kc0 + j] = (maskS[kc0 + j] > 0.f) ? acc[j] * 0.125f : -1e9f;

#pragma unroll
    for (int i = 0; i < 4; i++) {
        int t4 = tid + i * 256;
        int row = t4 >> 4, c4 = t4 & 15;
        int gt = base + row;
        float4 vv = make_float4(0.f, 0.f, 0.f, 0.f);
        if (gt >= 0 && gt < Tt)
            vv = ((const float4*)(v + ((size_t)(b * Tt + gt)) * Dm + h * HDm))[c4];
        ((float4*)(buf1 + row * 64))[c4] = vv;
    }
    __syncthreads();

    if (tid < 64) {
        float* row = buf0 + tid * 64;
        float m = -1e30f;
#pragma unroll 8
        for (int i2 = 0; i2 < 64; i2++) m = fmaxf(m, row[i2]);
        float s = 0.f;
#pragma unroll 8
        for (int i2 = 0; i2 < 64; i2++) { float e = expf(row[i2] - m); row[i2] = e; s += e; }
        float inv = 1.f / s;
#pragma unroll 8
        for (int i2 = 0; i2 < 64; i2++) row[i2] *= inv;
    }
    __syncthreads();

    float o[16];
#pragma unroll
    for (int j = 0; j < 16; j++) o[j] = 0.f;
    for (int kk = 0; kk < 64; kk++) {
        float p = buf0[qr * 64 + kk];
#pragma unroll
        for (int j4 = 0; j4 < 4; j4++) {
            float4 vv = ((float4*)(buf1 + kk * 64 + kc0))[j4];
            o[j4 * 4 + 0] += p * vv.x;
            o[j4 * 4 + 1] += p * vv.y;
            o[j4 * 4 + 2] += p * vv.z;
            o[j4 * 4 + 3] += p * vv.w;
        }
    }
    int gt = base + qr;
    if (gt >= 0 && gt < Tt) {
        size_t ob = ((size_t)(b * Tt + gt)) * Dm + h * HDm + kc0;
#pragma unroll
        for (int j = 0; j < 16; j += 2) {
            __nv_bfloat16 h0, l0, h1, l1;
            bfsplit(o[j], h0, l0);
            bfsplit(o[j + 1], h1, l1);
            *(__nv_bfloat162*)(ahi + ob + j) = __halves2bfloat162(h0, h1);
            *(__nv_bfloat162*)(alo + ob + j) = __halves2bfloat162(l0, l1);
        }
    }
}

// ============================================================
// Host driver
// ============================================================
extern "C" void kernel_launch(void* const* d_in, const int* in_sizes, int n_in,
                              void* d_out, int out_size) {
    const int*   inputs = (const int*)  d_in[0];
    const float* embed  = (const float*)d_in[1];
    const float* wq     = (const float*)d_in[2];
    const float* wk     = (const float*)d_in[3];
    const float* wv     = (const float*)d_in[4];
    const float* wo     = (const float*)d_in[5];
    const float* ln1_s  = (const float*)d_in[6];
    const float* ln1_b  = (const float*)d_in[7];
    const float* ln2_s  = (const float*)d_in[8];
    const float* ln2_b  = (const float*)d_in[9];
    const float* w1     = (const float*)d_in[10];
    const float* b1     = (const float*)d_in[11];
    const float* w2     = (const float*)d_in[12];
    const float* b2     = (const float*)d_in[13];
    const float* lnf_s  = (const float*)d_in[14];
    const float* lnf_b  = (const float*)d_in[15];

    float *x, *q, *k, *v;
    __nv_bfloat16 *hhi, *hlo, *ahi, *alo, *mhi, *mlo, *whi, *wlo;
    cudaGetSymbolAddress((void**)&x,   g_x);
    cudaGetSymbolAddress((void**)&q,   g_q);
    cudaGetSymbolAddress((void**)&k,   g_k);
    cudaGetSymbolAddress((void**)&v,   g_v);
    cudaGetSymbolAddress((void**)&hhi, g_hhi);
    cudaGetSymbolAddress((void**)&hlo, g_hlo);
    cudaGetSymbolAddress((void**)&ahi, g_ahi);
    cudaGetSymbolAddress((void**)&alo, g_alo);
    cudaGetSymbolAddress((void**)&mhi, g_mhi);
    cudaGetSymbolAddress((void**)&mlo, g_mlo);
    cudaGetSymbolAddress((void**)&whi, g_whi);
    cudaGetSymbolAddress((void**)&wlo, g_wlo);

    cudaFuncSetAttribute(hgemm<false,false,false,true,false>, cudaFuncAttributeMaxDynamicSharedMemorySize, SMEM_GEMM);
    cudaFuncSetAttribute(hgemm<true, false,false,true,false>, cudaFuncAttributeMaxDynamicSharedMemorySize, SMEM_GEMM);
    cudaFuncSetAttribute(hgemm<false,true, true, false,true>, cudaFuncAttributeMaxDynamicSharedMemorySize, SMEM_GEMM);
    cudaFuncSetAttribute(hgemm<true, false,true, true, false>, cudaFuncAttributeMaxDynamicSharedMemorySize, SMEM_GEMM);

    dim3 wb(32, 8);
    wprep<<<dim3(Dm / 32, Dm / 32, Lnum), wb>>>(wq, whi + OFF_WQ, wlo + OFF_WQ, Dm, Dm);
    wprep<<<dim3(Dm / 32, Dm / 32, Lnum), wb>>>(wk, whi + OFF_WK, wlo + OFF_WK, Dm, Dm);
    wprep<<<dim3(Dm / 32, Dm / 32, Lnum), wb>>>(wv, whi + OFF_WV, wlo + OFF_WV, Dm, Dm);
    wprep<<<dim3(Dm / 32, Dm / 32, Lnum), wb>>>(wo, whi + OFF_WO, wlo + OFF_WO, Dm, Dm);
    wprep<<<dim3(MLPD / 32, Dm / 32, Lnum), wb>>>(w1, whi + OFF_W1, wlo + OFF_W1, Dm, MLPD);
    wprep<<<dim3(Dm / 32, MLPD / 32, Lnum), wb>>>(w2, whi + OFF_W2, wlo + OFF_W2, MLPD, Dm);

    embed_kernel<<<(TOK * Dm) / 256, 256>>>(inputs, embed, x);

    dim3 gP(Dm / 128, TOK / 128);     // N=512 GEMMs
    dim3 gM1(MLPD / 128, TOK / 128);  // N=2048 GEMM

    for (int l = 0; l < Lnum; l++) {
        int lp = (l & 1) ? 32 : 0;
        int nb = (l & 1) ? (Tt + 64) / 64 : Tt / 64;

        ln_kernel<true><<<TOK, 128>>>(x, ln1_s + l * Dm, ln1_b + l * Dm,
                                      nullptr, hhi, hlo);

        const __nv_bfloat16* wqh = whi + OFF_WQ + (size_t)l * WSZP;
        const __nv_bfloat16* wql = wlo + OFF_WQ + (size_t)l * WSZP;
        const __nv_bfloat16* wkh = whi + OFF_WK + (size_t)l * WSZP;
        const __nv_bfloat16* wkl = wlo + OFF_WK + (size_t)l * WSZP;
        const __nv_bfloat16* wvh = whi + OFF_WV + (size_t)l * WSZP;
        const __nv_bfloat16* wvl = wlo + OFF_WV + (size_t)l * WSZP;
        const __nv_bfloat16* woh = whi + OFF_WO + (size_t)l * WSZP;
        const __nv_bfloat16* wol = wlo + OFF_WO + (size_t)l * WSZP;

        hgemm<false,false,false,true,false><<<gP, 256, SMEM_GEMM>>>(
            hhi, hlo, wqh, wql, nullptr, q, nullptr, nullptr, Dm, Dm);
        hgemm<false,false,false,true,false><<<gP, 256, SMEM_GEMM>>>(
            hhi, hlo, wkh, wkl, nullptr, k, nullptr, nullptr, Dm, Dm);
        hgemm<false,false,false,true,false><<<gP, 256, SMEM_GEMM>>>(
            hhi, hlo, wvh, wvl, nullptr, v, nullptr, nullptr, Dm, Dm);

        attn_kernel<<<dim3(nb, Hh, Bb), 256>>>(q, k, v, inputs, ahi, alo, lp);

        hgemm<true,false,false,true,false><<<gP, 256, SMEM_GEMM>>>(
            ahi, alo, woh, wol, nullptr, x, nullptr, nullptr, Dm, Dm);

        ln_kernel<true><<<TOK, 128>>>(x, ln2_s + l * Dm, ln2_b + l * Dm,
                                      nullptr, hhi, hlo);

        hgemm<false,true,true,false,true><<<gM1, 256, SMEM_GEMM>>>(
            hhi, hlo,
            whi + OFF_W1 + (size_t)l * WSZM, wlo + OFF_W1 + (size_t)l * WSZM,
            b1 + (size_t)l * MLPD, nullptr, mhi, mlo, MLPD, Dm);

        hgemm<true,false,true,true,false><<<gP, 256, SMEM_GEMM>>>(
            mhi, mlo,
            whi + OFF_W2 + (size_t)l * WSZM, wlo + OFF_W2 + (size_t)l * WSZM,
            b2 + (size_t)l * Dm, x, nullptr, nullptr, Dm, MLPD);
    }

    ln_kernel<false><<<TOK, 128>>>(x, lnf_s, lnf_b, (float*)d_out, nullptr, nullptr);
}

// round 4
// speedup vs baseline: 2.3549x; 1.0108x over previous
#include <cuda_runtime.h>
#include <cuda_bf16.h>
#include <math.h>
#include <stdint.h>

#define TOK   16384
#define Dm    512
#define Tt    4096
#define Bb    4
#define Hh    8
#define HDm   64
#define Lnum  6
#define MLPD  2048

#define WSZP  (Dm*Dm)          // 262144
#define WSZM  (Dm*MLPD)        // 1048576
#define SZ_QKV (3*WSZP)        // 786432
#define OFF_QKV 0
#define OFF_WO (6*SZ_QKV)                 // 4718592
#define OFF_W1 (OFF_WO + 6*WSZP)          // 6291456
#define OFF_W2 (OFF_W1 + 6*WSZM)          // 12582912
#define WTOT   (OFF_W2 + 6*WSZM)          // 18874368

// ---------------- scratch (device globals) ----------------
__device__ __align__(128) float g_x[TOK * Dm];
__device__ __align__(128) float g_qkv[TOK * 3 * Dm];
__device__ __align__(128) __nv_bfloat16 g_hhi[TOK * Dm];
__device__ __align__(128) __nv_bfloat16 g_hlo[TOK * Dm];
__device__ __align__(128) __nv_bfloat16 g_ahi[TOK * Dm];
__device__ __align__(128) __nv_bfloat16 g_alo[TOK * Dm];
__device__ __align__(128) __nv_bfloat16 g_mhi[(size_t)TOK * MLPD];
__device__ __align__(128) __nv_bfloat16 g_mlo[(size_t)TOK * MLPD];
__device__ __align__(128) __nv_bfloat16 g_whi[WTOT];
__device__ __align__(128) __nv_bfloat16 g_wlo[WTOT];

// ---------------- helpers ----------------
__device__ __forceinline__ uint32_t smem_u32(const void* p) {
    uint32_t a;
    asm("{ .reg .u64 t; cvta.to.shared.u64 t, %1; cvt.u32.u64 %0, t; }" : "=r"(a) : "l"(p));
    return a;
}
#define SWZ(o) ((o) ^ (((o) >> 3) & 0x70))

#define CP16(dst, src) \
    asm volatile("cp.async.cg.shared.global [%0], [%1], 16;" :: "r"(dst), "l"(src) : "memory")
#define CP_COMMIT() asm volatile("cp.async.commit_group;" ::: "memory")
#define CP_WAIT(n)  asm volatile("cp.async.wait_group %0;" :: "n"(n) : "memory")

__device__ __forceinline__ void ldsm4(uint32_t* r, uint32_t a) {
    asm volatile("ldmatrix.sync.aligned.m8n8.x4.shared.b16 {%0,%1,%2,%3}, [%4];"
                 : "=r"(r[0]), "=r"(r[1]), "=r"(r[2]), "=r"(r[3]) : "r"(a));
}
__device__ __forceinline__ void mma16816(float* c, const uint32_t* a,
                                         uint32_t b0, uint32_t b1) {
    asm volatile("mma.sync.aligned.m16n8k16.row.col.f32.bf16.bf16.f32 "
                 "{%0,%1,%2,%3},{%4,%5,%6,%7},{%8,%9},{%0,%1,%2,%3};"
                 : "+f"(c[0]), "+f"(c[1]), "+f"(c[2]), "+f"(c[3])
                 : "r"(a[0]), "r"(a[1]), "r"(a[2]), "r"(a[3]), "r"(b0), "r"(b1));
}
__device__ __forceinline__ void bfsplit(float x, __nv_bfloat16& h, __nv_bfloat16& l) {
    h = __float2bfloat16(x);
    l = __float2bfloat16(x - __bfloat162float(h));
}

// ============================================================
// Embedding + PE
// ============================================================
__global__ void embed_kernel(const int* __restrict__ inputs,
                             const float* __restrict__ embed,
                             float* __restrict__ x) {
    size_t id = (size_t)blockIdx.x * blockDim.x + threadIdx.x;
    int token = (int)(id >> 9);
    int d = (int)(id & 511);
    int pos = token & (Tt - 1);
    int tok = inputs[token];
    int i = (d < 256) ? d : d - 256;
    const float c = (float)(-9.210340371976184 / 512.0);
    float div = expf((float)(2 * i) * c);
    float ang = (float)pos * div;
    float pe = (d < 256) ? sinf(ang) : cosf(ang);
    x[id] = embed[(size_t)tok * Dm + d] + pe;
}

// ============================================================
// Fused weight prep: all weights, ONE launch.
// src [K][N] fp32 -> dest [N][K] bf16 hi/lo (QKV packed to N=1536)
// ============================================================
__global__ void wprep_all(const float* __restrict__ wq, const float* __restrict__ wk,
                          const float* __restrict__ wv, const float* __restrict__ wo,
                          const float* __restrict__ w1, const float* __restrict__ w2,
                          __nv_bfloat16* __restrict__ hi, __nv_bfloat16* __restrict__ lo) {
    __shared__ float tt[32][33];
    int t = blockIdx.x;
    const float* src;
    __nv_bfloat16 *dh, *dl;
    int srcN, dstK, n0, k0, nd;

    if (t < 4608) {                       // wq/wk/wv -> packed QKV [1536][512]
        int g = t / 1536, r = t % 1536;
        int l = r >> 8, rr = r & 255;
        n0 = (rr & 15) << 5; k0 = (rr >> 4) << 5;
        const float* w = (g == 0) ? wq : (g == 1) ? wk : wv;
        src = w + (size_t)l * WSZP;
        dh = hi + OFF_QKV + (size_t)l * SZ_QKV;
        dl = lo + OFF_QKV + (size_t)l * SZ_QKV;
        srcN = 512; dstK = 512; nd = g * 512 + n0;
    } else if (t < 6144) {                // wo [512][512]
        int r = t - 4608;
        int l = r >> 8, rr = r & 255;
        n0 = (rr & 15) << 5; k0 = (rr >> 4) << 5;
        src = wo + (size_t)l * WSZP;
        dh = hi + OFF_WO + (size_t)l * WSZP;
        dl = lo + OFF_WO + (size_t)l * WSZP;
        srcN = 512; dstK = 512; nd = n0;
    } else if (t < 12288) {               // w1 [2048][512]
        int r = t - 6144;
        int l = r >> 10, rr = r & 1023;
        n0 = (rr & 63) << 5; k0 = (rr >> 6) << 5;
        src = w1 + (size_t)l * WSZM;
        dh = hi + OFF_W1 + (size_t)l * WSZM;
        dl = lo + OFF_W1 + (size_t)l * WSZM;
        srcN = 2048; dstK = 512; nd = n0;
    } else {                              // w2 [512][2048]
        int r = t - 12288;
        int l = r >> 10, rr = r & 1023;
        n0 = (rr & 15) << 5; k0 = (rr >> 4) << 5;
        src = w2 + (size_t)l * WSZM;
        dh = hi + OFF_W2 + (size_t)l * WSZM;
        dl = lo + OFF_W2 + (size_t)l * WSZM;
        srcN = 512; dstK = 2048; nd = n0;
    }

    int tx = threadIdx.x, ty = threadIdx.y;
#pragma unroll
    for (int i = 0; i < 4; i++)
        tt[ty + i * 8][tx] = src[(size_t)(k0 + ty + i * 8) * srcN + n0 + tx];
    __syncthreads();
#pragma unroll
    for (int i = 0; i < 4; i++) {
        float v = tt[tx][ty + i * 8];
        __nv_bfloat16 h, L;
        bfsplit(v, h, L);
        size_t o = (size_t)(nd + ty + i * 8) * dstK + k0 + tx;
        dh[o] = h;
        dl[o] = L;
    }
}

// ============================================================
// LayerNorm
// ============================================================
template <bool WBF>
__global__ void ln_kernel(const float* __restrict__ x,
                          const float* __restrict__ sc,
                          const float* __restrict__ bi,
                          float* __restrict__ outf,
                          __nv_bfloat16* __restrict__ ohi,
                          __nv_bfloat16* __restrict__ olo) {
    __shared__ float red[4];
    int t = blockIdx.x;
    const float* xr = x + (size_t)t * Dm;
    float v[4];
    float sum = 0.f;
#pragma unroll
    for (int i = 0; i < 4; i++) { v[i] = xr[threadIdx.x + i * 128]; sum += v[i]; }
#pragma unroll
    for (int o = 16; o; o >>= 1) sum += __shfl_xor_sync(0xffffffffu, sum, o);
    if ((threadIdx.x & 31) == 0) red[threadIdx.x >> 5] = sum;
    __syncthreads();
    float mean = (red[0] + red[1] + red[2] + red[3]) * (1.f / Dm);
    __syncthreads();
    float sq = 0.f;
#pragma unroll
    for (int i = 0; i < 4; i++) { float d = v[i] - mean; sq += d * d; }
#pragma unroll
    for (int o = 16; o; o >>= 1) sq += __shfl_xor_sync(0xffffffffu, sq, o);
    if ((threadIdx.x & 31) == 0) red[threadIdx.x >> 5] = sq;
    __syncthreads();
    float var = (red[0] + red[1] + red[2] + red[3]) * (1.f / Dm);
    float rstd = rsqrtf(var + 1e-6f);
#pragma unroll
    for (int i = 0; i < 4; i++) {
        int idx = threadIdx.x + i * 128;
        float y = (v[i] - mean) * rstd * sc[idx] + bi[idx];
        if (WBF) {
            __nv_bfloat16 h, L;
            bfsplit(y, h, L);
            ohi[(size_t)t * Dm + idx] = h;
            olo[(size_t)t * Dm + idx] = L;
        } else {
            outf[(size_t)t * Dm + idx] = y;
        }
    }
}

// ============================================================
// HMMA bf16 split-precision GEMM, 3-stage cp.async pipeline
// C[M,N] (+)= (Ahi+Alo)[M,K] @ (Bhi+Blo)[N,K]^T  (drop lo*lo)
// Tile 128x128, K-chunk 64, 256 threads.
// ============================================================
#define ST_A_HI 0
#define ST_A_LO 16384
#define ST_B_HI 32768
#define ST_B_LO 49152
#define STAGE   65536
#define SMEM_GEMM (3 * STAGE)

template <bool ACCUM, bool RELU, bool BIAS, bool WF32, bool WBF>
__global__ void __launch_bounds__(256, 1)
hgemm(const __nv_bfloat16* __restrict__ Ahi, const __nv_bfloat16* __restrict__ Alo,
      const __nv_bfloat16* __restrict__ Bhi, const __nv_bfloat16* __restrict__ Blo,
      const float* __restrict__ bias, float* __restrict__ C,
      __nv_bfloat16* __restrict__ Ohi, __nv_bfloat16* __restrict__ Olo,
      int N, int K) {
    extern __shared__ char smem[];
    uint32_t sb = smem_u32(smem);
    int tid = threadIdx.x, wid = tid >> 5, lane = tid & 31;
    int m0 = blockIdx.y * 128, n0 = blockIdx.x * 128;
    int wm = (wid >> 1) * 32, wn = (wid & 1) * 64;

    float acc[2][8][4];
#pragma unroll
    for (int i = 0; i < 2; i++)
#pragma unroll
        for (int j = 0; j < 8; j++)
#pragma unroll
            for (int e = 0; e < 4; e++) acc[i][j][e] = 0.f;

    const int NC = K >> 6;

#define LOAD_CHUNK(c, s) do {                                                   \
    int kt = (c) << 6;                                                          \
    uint32_t st_ = sb + (s) * STAGE;                                            \
    _Pragma("unroll")                                                           \
    for (int i = 0; i < 4; i++) {                                               \
        int u = tid + i * 256;                                                  \
        int row = u >> 3, kc = u & 7;                                           \
        uint32_t so = SWZ((uint32_t)(row * 128 + kc * 16));                     \
        size_t ga = (size_t)(m0 + row) * K + kt + kc * 8;                       \
        size_t gb = (size_t)(n0 + row) * K + kt + kc * 8;                       \
        CP16(st_ + ST_A_HI + so, Ahi + ga);                                     \
        CP16(st_ + ST_A_LO + so, Alo + ga);                                     \
        CP16(st_ + ST_B_HI + so, Bhi + gb);                                     \
        CP16(st_ + ST_B_LO + so, Blo + gb);                                     \
    } } while (0)

    LOAD_CHUNK(0, 0);
    CP_COMMIT();
    LOAD_CHUNK(1, 1);
    CP_COMMIT();

    for (int c = 0; c < NC; c++) {
        if (c + 1 < NC) { CP_WAIT(1); } else { CP_WAIT(0); }
        __syncthreads();
        if (c + 2 < NC) {
            LOAD_CHUNK(c + 2, (c + 2) % 3);
            CP_COMMIT();
        }
        uint32_t st = sb + (c % 3) * STAGE;

#pragma unroll
        for (int ks = 0; ks < 4; ks++) {
            int kb = ks * 32 + ((lane >> 4) & 1) * 16;
            uint32_t ah[2][4], al[2][4], bh[4][4], bl[4][4];
#pragma unroll
            for (int mf = 0; mf < 2; mf++) {
                uint32_t ro = (uint32_t)((wm + mf * 16 + (lane & 15)) * 128 + kb);
                ldsm4(ah[mf], st + ST_A_HI + SWZ(ro));
                ldsm4(al[mf], st + ST_A_LO + SWZ(ro));
            }
#pragma unroll
            for (int nf = 0; nf < 4; nf++) {
                uint32_t ro = (uint32_t)((wn + nf * 16 + (lane & 15)) * 128 + kb);
                ldsm4(bh[nf], st + ST_B_HI + SWZ(ro));
                ldsm4(bl[nf], st + ST_B_LO + SWZ(ro));
            }
#pragma unroll
            for (int mf = 0; mf < 2; mf++)
#pragma unroll
                for (int nb = 0; nb < 8; nb++) {
                    int nf = nb >> 1, sl = nb & 1;
                    mma16816(acc[mf][nb], ah[mf], bh[nf][sl], bh[nf][sl + 2]);
                    mma16816(acc[mf][nb], ah[mf], bl[nf][sl], bl[nf][sl + 2]);
                    mma16816(acc[mf][nb], al[mf], bh[nf][sl], bh[nf][sl + 2]);
                }
        }
    }

    // epilogue
    int r0 = m0 + wm + (lane >> 2);
    int cb = n0 + wn + (lane & 3) * 2;
#pragma unroll
    for (int mf = 0; mf < 2; mf++)
#pragma unroll
        for (int half = 0; half < 2; half++) {
            int rr = r0 + mf * 16 + half * 8;
#pragma unroll
            for (int nb = 0; nb < 8; nb++) {
                int cc = cb + nb * 8;
                float v0 = acc[mf][nb][half * 2 + 0];
                float v1 = acc[mf][nb][half * 2 + 1];
                if (BIAS) {
                    float2 bv = *(const float2*)(bias + cc);
                    v0 += bv.x; v1 += bv.y;
                }
                if (RELU) { v0 = fmaxf(v0, 0.f); v1 = fmaxf(v1, 0.f); }
                if (ACCUM) {
                    float2 o = *(const float2*)(C + (size_t)rr * N + cc);
                    v0 += o.x; v1 += o.y;
                }
                if (WF32)
                    *(float2*)(C + (size_t)rr * N + cc) = make_float2(v0, v1);
                if (WBF) {
                    __nv_bfloat16 h0, l0, h1, l1;
                    bfsplit(v0, h0, l0);
                    bfsplit(v1, h1, l1);
                    *(__nv_bfloat162*)(Ohi + (size_t)rr * N + cc) = __halves2bfloat162(h0, h1);
                    *(__nv_bfloat162*)(Olo + (size_t)rr * N + cc) = __halves2bfloat162(l0, l1);
                }
            }
        }
}

// ============================================================
// Local block attention (reads packed qkv, stride 1536)
// ============================================================
__global__ void attn_kernel(const float* __restrict__ qkv,
                            const int* __restrict__ inputs,
                            __nv_bfloat16* __restrict__ ahi,
                            __nv_bfloat16* __restrict__ alo,
                            int lp) {
    __shared__ float buf0[64 * 64];
    __shared__ float buf1[64 * 64];
    __shared__ float maskS[64];

    int n = blockIdx.x, h = blockIdx.y, b = blockIdx.z;
    int tid = threadIdx.x;
    int base = n * 64 - lp;

#pragma unroll
    for (int i = 0; i < 4; i++) {
        int t4 = tid + i * 256;
        int row = t4 >> 4, c4 = t4 & 15;
        int gt = base + row;
        float4 qv = make_float4(0.f, 0.f, 0.f, 0.f);
        float4 kv = qv;
        if (gt >= 0 && gt < Tt) {
            size_t off = ((size_t)(b * Tt + gt)) * 1536 + h * HDm;
            qv = ((const float4*)(qkv + off))[c4];
            kv = ((const float4*)(qkv + off + 512))[c4];
        }
        ((float4*)(buf0 + row * 64))[c4] = qv;
        ((float4*)(buf1 + row * 64))[c4] = kv;
    }
    if (tid < 64) {
        int gt = base + tid;
        maskS[tid] = (gt >= 0 && gt < Tt && inputs[b * Tt + gt] > 0) ? 1.f : 0.f;
    }
    __syncthreads();

    int qr = tid >> 2;
    int kc0 = (tid & 3) * 16;
    float acc[16];
#pragma unroll
    for (int j = 0; j < 16; j++) acc[j] = 0.f;
#pragma unroll
    for (int f4 = 0; f4 < 16; f4++) {
        float4 qv = ((float4*)(buf0 + qr * 64))[f4];
#pragma unroll
        for (int j = 0; j < 16; j++) {
            float4 kv = ((float4*)(buf1 + (kc0 + j) * 64))[f4];
            acc[j] += qv.x * kv.x + qv.y * kv.y + qv.z * kv.z + qv.w * kv.w;
        }
    }
    __syncthreads();

#pragma unroll
    for (int j = 0; j < 16; j++)
        buf0[qr * 64 + kc0 + j] = (maskS[kc0 + j] > 0.f) ? acc[j] * 0.125f : -1e9f;

#pragma unroll
    for (int i = 0; i < 4; i++) {
        int t4 = tid + i * 256;
        int row = t4 >> 4, c4 = t4 & 15;
        int gt = base + row;
        float4 vv = make_float4(0.f, 0.f, 0.f, 0.f);
        if (gt >= 0 && gt < Tt)
            vv = ((const float4*)(qkv + ((size_t)(b * Tt + gt)) * 1536 + h * HDm + 1024))[c4];
        ((float4*)(buf1 + row * 64))[c4] = vv;
    }
    __syncthreads();

    if (tid < 64) {
        float* row = buf0 + tid * 64;
        float m = -1e30f;
#pragma unroll 8
        for (int i2 = 0; i2 < 64; i2++) m = fmaxf(m, row[i2]);
        float s = 0.f;
#pragma unroll 8
        for (int i2 = 0; i2 < 64; i2++) { float e = expf(row[i2] - m); row[i2] = e; s += e; }
        float inv = 1.f / s;
#pragma unroll 8
        for (int i2 = 0; i2 < 64; i2++) row[i2] *= inv;
    }
    __syncthreads();

    float o[16];
#pragma unroll
    for (int j = 0; j < 16; j++) o[j] = 0.f;
    for (int kk = 0; kk < 64; kk++) {
        float p = buf0[qr * 64 + kk];
#pragma unroll
        for (int j4 = 0; j4 < 4; j4++) {
            float4 vv = ((float4*)(buf1 + kk * 64 + kc0))[j4];
            o[j4 * 4 + 0] += p * vv.x;
            o[j4 * 4 + 1] += p * vv.y;
            o[j4 * 4 + 2] += p * vv.z;
            o[j4 * 4 + 3] += p * vv.w;
        }
    }
    int gt = base + qr;
    if (gt >= 0 && gt < Tt) {
        size_t ob = ((size_t)(b * Tt + gt)) * Dm + h * HDm + kc0;
#pragma unroll
        for (int j = 0; j < 16; j += 2) {
            __nv_bfloat16 h0, l0, h1, l1;
            bfsplit(o[j], h0, l0);
            bfsplit(o[j + 1], h1, l1);
            *(__nv_bfloat162*)(ahi + ob + j) = __halves2bfloat162(h0, h1);
            *(__nv_bfloat162*)(alo + ob + j) = __halves2bfloat162(l0, l1);
        }
    }
}

// ============================================================
// Host driver
// ============================================================
extern "C" void kernel_launch(void* const* d_in, const int* in_sizes, int n_in,
                              void* d_out, int out_size) {
    const int*   inputs = (const int*)  d_in[0];
    const float* embed  = (const float*)d_in[1];
    const float* wq     = (const float*)d_in[2];
    const float* wk     = (const float*)d_in[3];
    const float* wv     = (const float*)d_in[4];
    const float* wo     = (const float*)d_in[5];
    const float* ln1_s  = (const float*)d_in[6];
    const float* ln1_b  = (const float*)d_in[7];
    const float* ln2_s  = (const float*)d_in[8];
    const float* ln2_b  = (const float*)d_in[9];
    const float* w1     = (const float*)d_in[10];
    const float* b1     = (const float*)d_in[11];
    const float* w2     = (const float*)d_in[12];
    const float* b2     = (const float*)d_in[13];
    const float* lnf_s  = (const float*)d_in[14];
    const float* lnf_b  = (const float*)d_in[15];

    float *x, *qkv;
    __nv_bfloat16 *hhi, *hlo, *ahi, *alo, *mhi, *mlo, *whi, *wlo;
    cudaGetSymbolAddress((void**)&x,   g_x);
    cudaGetSymbolAddress((void**)&qkv, g_qkv);
    cudaGetSymbolAddress((void**)&hhi, g_hhi);
    cudaGetSymbolAddress((void**)&hlo, g_hlo);
    cudaGetSymbolAddress((void**)&ahi, g_ahi);
    cudaGetSymbolAddress((void**)&alo, g_alo);
    cudaGetSymbolAddress((void**)&mhi, g_mhi);
    cudaGetSymbolAddress((void**)&mlo, g_mlo);
    cudaGetSymbolAddress((void**)&whi, g_whi);
    cudaGetSymbolAddress((void**)&wlo, g_wlo);

    cudaFuncSetAttribute(hgemm<false,false,false,true,false>, cudaFuncAttributeMaxDynamicSharedMemorySize, SMEM_GEMM);
    cudaFuncSetAttribute(hgemm<true, false,false,true,false>, cudaFuncAttributeMaxDynamicSharedMemorySize, SMEM_GEMM);
    cudaFuncSetAttribute(hgemm<false,true, true, false,true>, cudaFuncAttributeMaxDynamicSharedMemorySize, SMEM_GEMM);
    cudaFuncSetAttribute(hgemm<true, false,true, true, false>, cudaFuncAttributeMaxDynamicSharedMemorySize, SMEM_GEMM);

    wprep_all<<<18432, dim3(32, 8)>>>(wq, wk, wv, wo, w1, w2, whi, wlo);
    embed_kernel<<<(TOK * Dm) / 256, 256>>>(inputs, embed, x);

    dim3 gQKV(1536 / 128, TOK / 128);
    dim3 gP(Dm / 128, TOK / 128);
    dim3 gM1(MLPD / 128, TOK / 128);

    for (int l = 0; l < Lnum; l++) {
        int lp = (l & 1) ? 32 : 0;
        int nb = (l & 1) ? (Tt + 64) / 64 : Tt / 64;

        ln_kernel<true><<<TOK, 128>>>(x, ln1_s + l * Dm, ln1_b + l * Dm,
                                      nullptr, hhi, hlo);

        // qkv = h @ [wq|wk|wv]
        hgemm<false,false,false,true,false><<<gQKV, 256, SMEM_GEMM>>>(
            hhi, hlo,
            whi + OFF_QKV + (size_t)l * SZ_QKV, wlo + OFF_QKV + (size_t)l * SZ_QKV,
            nullptr, qkv, nullptr, nullptr, 1536, Dm);

        attn_kernel<<<dim3(nb, Hh, Bb), 256>>>(qkv, inputs, ahi, alo, lp);

        // x += attn @ wo
        hgemm<true,false,false,true,false><<<gP, 256, SMEM_GEMM>>>(
            ahi, alo,
            whi + OFF_WO + (size_t)l * WSZP, wlo + OFF_WO + (size_t)l * WSZP,
            nullptr, x, nullptr, nullptr, Dm, Dm);

        ln_kernel<true><<<TOK, 128>>>(x, ln2_s + l * Dm, ln2_b + l * Dm,
                                      nullptr, hhi, hlo);

        // mlp = relu(h @ w1 + b1)
        hgemm<false,true,true,false,true><<<gM1, 256, SMEM_GEMM>>>(
            hhi, hlo,
            whi + OFF_W1 + (size_t)l * WSZM, wlo + OFF_W1 + (size_t)l * WSZM,
            b1 + (size_t)l * MLPD, nullptr, mhi, mlo, MLPD, Dm);

        // x += mlp @ w2 + b2
        hgemm<true,false,true,true,false><<<gP, 256, SMEM_GEMM>>>(
            mhi, mlo,
            whi + OFF_W2 + (size_t)l * WSZM, wlo + OFF_W2 + (size_t)l * WSZM,
            b2 + (size_t)l * Dm, x, nullptr, nullptr, Dm, MLPD);
    }

    ln_kernel<false><<<TOK, 128>>>(x, lnf_s, lnf_b, (float*)d_out, nullptr, nullptr);
}

// round 5
// speedup vs baseline: 2.4492x; 1.0400x over previous
#include <cuda_runtime.h>
#include <cuda_bf16.h>
#include <math.h>
#include <stdint.h>

#define TOK   16384
#define Dm    512
#define Tt    4096
#define Bb    4
#define Hh    8
#define HDm   64
#define Lnum  6
#define MLPD  2048

#define WSZP  (Dm*Dm)
#define WSZM  (Dm*MLPD)
#define SZ_QKV (3*WSZP)
#define OFF_QKV 0
#define OFF_WO (6*SZ_QKV)
#define OFF_W1 (OFF_WO + 6*WSZP)
#define OFF_W2 (OFF_W1 + 6*WSZM)
#define WTOT   (OFF_W2 + 6*WSZM)

// ---------------- scratch (device globals) ----------------
__device__ __align__(128) float g_x[TOK * Dm];
__device__ __align__(128) float g_qkv[TOK * 3 * Dm];
__device__ __align__(128) __nv_bfloat16 g_hhi[TOK * Dm];
__device__ __align__(128) __nv_bfloat16 g_hlo[TOK * Dm];
__device__ __align__(128) __nv_bfloat16 g_ahi[TOK * Dm];
__device__ __align__(128) __nv_bfloat16 g_alo[TOK * Dm];
__device__ __align__(128) __nv_bfloat16 g_mhi[(size_t)TOK * MLPD];
__device__ __align__(128) __nv_bfloat16 g_mlo[(size_t)TOK * MLPD];
__device__ __align__(128) __nv_bfloat16 g_whi[WTOT];
__device__ __align__(128) __nv_bfloat16 g_wlo[WTOT];

// ---------------- helpers ----------------
__device__ __forceinline__ uint32_t smem_u32(const void* p) {
    uint32_t a;
    asm("{ .reg .u64 t; cvta.to.shared.u64 t, %1; cvt.u32.u64 %0, t; }" : "=r"(a) : "l"(p));
    return a;
}
#define SWZ(o) ((o) ^ (((o) >> 3) & 0x70))

#define CP16(dst, src) \
    asm volatile("cp.async.cg.shared.global [%0], [%1], 16;" :: "r"(dst), "l"(src) : "memory")
#define CP_COMMIT() asm volatile("cp.async.commit_group;" ::: "memory")
#define CP_WAIT(n)  asm volatile("cp.async.wait_group %0;" :: "n"(n) : "memory")

__device__ __forceinline__ void ldsm4(uint32_t* r, uint32_t a) {
    asm volatile("ldmatrix.sync.aligned.m8n8.x4.shared.b16 {%0,%1,%2,%3}, [%4];"
                 : "=r"(r[0]), "=r"(r[1]), "=r"(r[2]), "=r"(r[3]) : "r"(a));
}
__device__ __forceinline__ void mma16816(float* c, const uint32_t* a,
                                         uint32_t b0, uint32_t b1) {
    asm volatile("mma.sync.aligned.m16n8k16.row.col.f32.bf16.bf16.f32 "
                 "{%0,%1,%2,%3},{%4,%5,%6,%7},{%8,%9},{%0,%1,%2,%3};"
                 : "+f"(c[0]), "+f"(c[1]), "+f"(c[2]), "+f"(c[3])
                 : "r"(a[0]), "r"(a[1]), "r"(a[2]), "r"(a[3]), "r"(b0), "r"(b1));
}
__device__ __forceinline__ void bfsplit(float x, __nv_bfloat16& h, __nv_bfloat16& l) {
    h = __float2bfloat16(x);
    l = __float2bfloat16(x - __bfloat162float(h));
}

// ============================================================
// Embedding + PE
// ============================================================
__global__ void embed_kernel(const int* __restrict__ inputs,
                             const float* __restrict__ embed,
                             float* __restrict__ x) {
    size_t id = (size_t)blockIdx.x * blockDim.x + threadIdx.x;
    int token = (int)(id >> 9);
    int d = (int)(id & 511);
    int pos = token & (Tt - 1);
    int tok = inputs[token];
    int i = (d < 256) ? d : d - 256;
    const float c = (float)(-9.210340371976184 / 512.0);
    float div = expf((float)(2 * i) * c);
    float ang = (float)pos * div;
    float pe = (d < 256) ? sinf(ang) : cosf(ang);
    x[id] = embed[(size_t)tok * Dm + d] + pe;
}

// ============================================================
// Fused weight prep (one launch)
// ============================================================
__global__ void wprep_all(const float* __restrict__ wq, const float* __restrict__ wk,
                          const float* __restrict__ wv, const float* __restrict__ wo,
                          const float* __restrict__ w1, const float* __restrict__ w2,
                          __nv_bfloat16* __restrict__ hi, __nv_bfloat16* __restrict__ lo) {
    __shared__ float tt[32][33];
    int t = blockIdx.x;
    const float* src;
    __nv_bfloat16 *dh, *dl;
    int srcN, dstK, n0, k0, nd;

    if (t < 4608) {
        int g = t / 1536, r = t % 1536;
        int l = r >> 8, rr = r & 255;
        n0 = (rr & 15) << 5; k0 = (rr >> 4) << 5;
        const float* w = (g == 0) ? wq : (g == 1) ? wk : wv;
        src = w + (size_t)l * WSZP;
        dh = hi + OFF_QKV + (size_t)l * SZ_QKV;
        dl = lo + OFF_QKV + (size_t)l * SZ_QKV;
        srcN = 512; dstK = 512; nd = g * 512 + n0;
    } else if (t < 6144) {
        int r = t - 4608;
        int l = r >> 8, rr = r & 255;
        n0 = (rr & 15) << 5; k0 = (rr >> 4) << 5;
        src = wo + (size_t)l * WSZP;
        dh = hi + OFF_WO + (size_t)l * WSZP;
        dl = lo + OFF_WO + (size_t)l * WSZP;
        srcN = 512; dstK = 512; nd = n0;
    } else if (t < 12288) {
        int r = t - 6144;
        int l = r >> 10, rr = r & 1023;
        n0 = (rr & 63) << 5; k0 = (rr >> 6) << 5;
        src = w1 + (size_t)l * WSZM;
        dh = hi + OFF_W1 + (size_t)l * WSZM;
        dl = lo + OFF_W1 + (size_t)l * WSZM;
        srcN = 2048; dstK = 512; nd = n0;
    } else {
        int r = t - 12288;
        int l = r >> 10, rr = r & 1023;
        n0 = (rr & 15) << 5; k0 = (rr >> 4) << 5;
        src = w2 + (size_t)l * WSZM;
        dh = hi + OFF_W2 + (size_t)l * WSZM;
        dl = lo + OFF_W2 + (size_t)l * WSZM;
        srcN = 512; dstK = 2048; nd = n0;
    }

    int tx = threadIdx.x, ty = threadIdx.y;
#pragma unroll
    for (int i = 0; i < 4; i++)
        tt[ty + i * 8][tx] = src[(size_t)(k0 + ty + i * 8) * srcN + n0 + tx];
    __syncthreads();
#pragma unroll
    for (int i = 0; i < 4; i++) {
        float v = tt[tx][ty + i * 8];
        __nv_bfloat16 h, L;
        bfsplit(v, h, L);
        size_t o = (size_t)(nd + ty + i * 8) * dstK + k0 + tx;
        dh[o] = h;
        dl[o] = L;
    }
}

// ============================================================
// LayerNorm
// ============================================================
template <bool WBF>
__global__ void ln_kernel(const float* __restrict__ x,
                          const float* __restrict__ sc,
                          const float* __restrict__ bi,
                          float* __restrict__ outf,
                          __nv_bfloat16* __restrict__ ohi,
                          __nv_bfloat16* __restrict__ olo) {
    __shared__ float red[4];
    int t = blockIdx.x;
    const float* xr = x + (size_t)t * Dm;
    float v[4];
    float sum = 0.f;
#pragma unroll
    for (int i = 0; i < 4; i++) { v[i] = xr[threadIdx.x + i * 128]; sum += v[i]; }
#pragma unroll
    for (int o = 16; o; o >>= 1) sum += __shfl_xor_sync(0xffffffffu, sum, o);
    if ((threadIdx.x & 31) == 0) red[threadIdx.x >> 5] = sum;
    __syncthreads();
    float mean = (red[0] + red[1] + red[2] + red[3]) * (1.f / Dm);
    __syncthreads();
    float sq = 0.f;
#pragma unroll
    for (int i = 0; i < 4; i++) { float d = v[i] - mean; sq += d * d; }
#pragma unroll
    for (int o = 16; o; o >>= 1) sq += __shfl_xor_sync(0xffffffffu, sq, o);
    if ((threadIdx.x & 31) == 0) red[threadIdx.x >> 5] = sq;
    __syncthreads();
    float var = (red[0] + red[1] + red[2] + red[3]) * (1.f / Dm);
    float rstd = rsqrtf(var + 1e-6f);
#pragma unroll
    for (int i = 0; i < 4; i++) {
        int idx = threadIdx.x + i * 128;
        float y = (v[i] - mean) * rstd * sc[idx] + bi[idx];
        if (WBF) {
            __nv_bfloat16 h, L;
            bfsplit(y, h, L);
            ohi[(size_t)t * Dm + idx] = h;
            olo[(size_t)t * Dm + idx] = L;
        } else {
            outf[(size_t)t * Dm + idx] = y;
        }
    }
}

// ============================================================
// HMMA bf16 split-precision GEMM
// CTA tile 256x128, warp tile 32x64, 16 warps (512 thr),
// K-chunk 64, 2-stage cp.async (96KB/stage).
// ============================================================
#define ST_A_HI 0
#define ST_A_LO 32768
#define ST_B_HI 65536
#define ST_B_LO 81920
#define STAGE   98304
#define SMEM_GEMM (2 * STAGE)

template <bool ACCUM, bool RELU, bool BIAS, bool WF32, bool WBF>
__global__ void __launch_bounds__(512, 1)
hgemm(const __nv_bfloat16* __restrict__ Ahi, const __nv_bfloat16* __restrict__ Alo,
      const __nv_bfloat16* __restrict__ Bhi, const __nv_bfloat16* __restrict__ Blo,
      const float* __restrict__ bias, float* __restrict__ C,
      __nv_bfloat16* __restrict__ Ohi, __nv_bfloat16* __restrict__ Olo,
      int N, int K) {
    extern __shared__ char smem[];
    uint32_t sb = smem_u32(smem);
    int tid = threadIdx.x, wid = tid >> 5, lane = tid & 31;
    int m0 = blockIdx.y * 256, n0 = blockIdx.x * 128;
    int wm = (wid >> 1) * 32, wn = (wid & 1) * 64;

    float acc[2][8][4];
#pragma unroll
    for (int i = 0; i < 2; i++)
#pragma unroll
        for (int j = 0; j < 8; j++)
#pragma unroll
            for (int e = 0; e < 4; e++) acc[i][j][e] = 0.f;

    const int NC = K >> 6;

#define LOAD_CHUNK(c, s) do {                                                   \
    int kt = (c) << 6;                                                          \
    uint32_t st_ = sb + (s) * STAGE;                                            \
    _Pragma("unroll")                                                           \
    for (int i = 0; i < 4; i++) {   /* A: 256 rows, hi+lo */                    \
        int u = tid + i * 512;                                                  \
        int row = u >> 3, kc = u & 7;                                           \
        uint32_t so = SWZ((uint32_t)(row * 128 + kc * 16));                     \
        size_t ga = (size_t)(m0 + row) * K + kt + kc * 8;                       \
        CP16(st_ + ST_A_HI + so, Ahi + ga);                                     \
        CP16(st_ + ST_A_LO + so, Alo + ga);                                     \
    }                                                                           \
    _Pragma("unroll")                                                           \
    for (int i = 0; i < 2; i++) {   /* B: 128 rows, hi+lo */                    \
        int u = tid + i * 512;                                                  \
        int row = u >> 3, kc = u & 7;                                           \
        uint32_t so = SWZ((uint32_t)(row * 128 + kc * 16));                     \
        size_t gb = (size_t)(n0 + row) * K + kt + kc * 8;                       \
        CP16(st_ + ST_B_HI + so, Bhi + gb);                                     \
        CP16(st_ + ST_B_LO + so, Blo + gb);                                     \
    } } while (0)

    LOAD_CHUNK(0, 0);
    CP_COMMIT();
    LOAD_CHUNK(1, 1);
    CP_COMMIT();

    for (int c = 0; c < NC; c++) {
        if (c + 1 < NC) { CP_WAIT(1); } else { CP_WAIT(0); }
        __syncthreads();
        uint32_t st = sb + (c & 1) * STAGE;

#pragma unroll
        for (int ks = 0; ks < 4; ks++) {
            int kb = ks * 32 + ((lane >> 4) & 1) * 16;
            uint32_t ah[2][4], al[2][4];
#pragma unroll
            for (int mf = 0; mf < 2; mf++) {
                uint32_t ro = (uint32_t)((wm + mf * 16 + (lane & 15)) * 128 + kb);
                ldsm4(ah[mf], st + ST_A_HI + SWZ(ro));
                ldsm4(al[mf], st + ST_A_LO + SWZ(ro));
            }
#pragma unroll
            for (int nf = 0; nf < 4; nf++) {
                uint32_t bh[4], bl[4];
                uint32_t ro = (uint32_t)((wn + nf * 16 + (lane & 15)) * 128 + kb);
                ldsm4(bh, st + ST_B_HI + SWZ(ro));
                ldsm4(bl, st + ST_B_LO + SWZ(ro));
#pragma unroll
                for (int mf = 0; mf < 2; mf++)
#pragma unroll
                    for (int sl = 0; sl < 2; sl++) {
                        int nb = nf * 2 + sl;
                        mma16816(acc[mf][nb], ah[mf], bh[sl], bh[sl + 2]);
                        mma16816(acc[mf][nb], ah[mf], bl[sl], bl[sl + 2]);
                        mma16816(acc[mf][nb], al[mf], bh[sl], bh[sl + 2]);
                    }
            }
        }
        __syncthreads();
        if (c + 2 < NC) {
            LOAD_CHUNK(c + 2, c & 1);
            CP_COMMIT();
        }
    }

    // epilogue
    int r0 = m0 + wm + (lane >> 2);
    int cb = n0 + wn + (lane & 3) * 2;
#pragma unroll
    for (int mf = 0; mf < 2; mf++)
#pragma unroll
        for (int half = 0; half < 2; half++) {
            int rr = r0 + mf * 16 + half * 8;
#pragma unroll
            for (int nb = 0; nb < 8; nb++) {
                int cc = cb + nb * 8;
                float v0 = acc[mf][nb][half * 2 + 0];
                float v1 = acc[mf][nb][half * 2 + 1];
                if (BIAS) {
                    float2 bv = *(const float2*)(bias + cc);
                    v0 += bv.x; v1 += bv.y;
                }
                if (RELU) { v0 = fmaxf(v0, 0.f); v1 = fmaxf(v1, 0.f); }
                if (ACCUM) {
                    float2 o = *(const float2*)(C + (size_t)rr * N + cc);
                    v0 += o.x; v1 += o.y;
                }
                if (WF32)
                    *(float2*)(C + (size_t)rr * N + cc) = make_float2(v0, v1);
                if (WBF) {
                    __nv_bfloat16 h0, l0, h1, l1;
                    bfsplit(v0, h0, l0);
                    bfsplit(v1, h1, l1);
                    *(__nv_bfloat162*)(Ohi + (size_t)rr * N + cc) = __halves2bfloat162(h0, h1);
                    *(__nv_bfloat162*)(Olo + (size_t)rr * N + cc) = __halves2bfloat162(l0, l1);
                }
            }
        }
}

// ============================================================
// Local block attention (reads packed qkv, stride 1536)
// ============================================================
__global__ void attn_kernel(const float* __restrict__ qkv,
                            const int* __restrict__ inputs,
                            __nv_bfloat16* __restrict__ ahi,
                            __nv_bfloat16* __restrict__ alo,
                            int lp) {
    __shared__ float buf0[64 * 64];
    __shared__ float buf1[64 * 64];
    __shared__ float maskS[64];

    int n = blockIdx.x, h = blockIdx.y, b = blockIdx.z;
    int tid = threadIdx.x;
    int base = n * 64 - lp;

#pragma unroll
    for (int i = 0; i < 4; i++) {
        int t4 = tid + i * 256;
        int row = t4 >> 4, c4 = t4 & 15;
        int gt = base + row;
        float4 qv = make_float4(0.f, 0.f, 0.f, 0.f);
        float4 kv = qv;
        if (gt >= 0 && gt < Tt) {
            size_t off = ((size_t)(b * Tt + gt)) * 1536 + h * HDm;
            qv = ((const float4*)(qkv + off))[c4];
            kv = ((const float4*)(qkv + off + 512))[c4];
        }
        ((float4*)(buf0 + row * 64))[c4] = qv;
        ((float4*)(buf1 + row * 64))[c4] = kv;
    }
    if (tid < 64) {
        int gt = base + tid;
        maskS[tid] = (gt >= 0 && gt < Tt && inputs[b * Tt + gt] > 0) ? 1.f : 0.f;
    }
    __syncthreads();

    int qr = tid >> 2;
    int kc0 = (tid & 3) * 16;
    float acc[16];
#pragma unroll
    for (int j = 0; j < 16; j++) acc[j] = 0.f;
#pragma unroll
    for (int f4 = 0; f4 < 16; f4++) {
        float4 qv = ((float4*)(buf0 + qr * 64))[f4];
#pragma unroll
        for (int j = 0; j < 16; j++) {
            float4 kv = ((float4*)(buf1 + (kc0 + j) * 64))[f4];
            acc[j] += qv.x * kv.x + qv.y * kv.y + qv.z * kv.z + qv.w * kv.w;
        }
    }
    __syncthreads();

#pragma unroll
    for (int j = 0; j < 16; j++)
        buf0[qr * 64 + kc0 + j] = (maskS[kc0 + j] > 0.f) ? acc[j] * 0.125f : -1e9f;

#pragma unroll
    for (int i = 0; i < 4; i++) {
        int t4 = tid + i * 256;
        int row = t4 >> 4, c4 = t4 & 15;
        int gt = base + row;
        float4 vv = make_float4(0.f, 0.f, 0.f, 0.f);
        if (gt >= 0 && gt < Tt)
            vv = ((const float4*)(qkv + ((size_t)(b * Tt + gt)) * 1536 + h * HDm + 1024))[c4];
        ((float4*)(buf1 + row * 64))[c4] = vv;
    }
    __syncthreads();

    if (tid < 64) {
        float* row = buf0 + tid * 64;
        float m = -1e30f;
#pragma unroll 8
        for (int i2 = 0; i2 < 64; i2++) m = fmaxf(m, row[i2]);
        float s = 0.f;
#pragma unroll 8
        for (int i2 = 0; i2 < 64; i2++) { float e = expf(row[i2] - m); row[i2] = e; s += e; }
        float inv = 1.f / s;
#pragma unroll 8
        for (int i2 = 0; i2 < 64; i2++) row[i2] *= inv;
    }
    __syncthreads();

    float o[16];
#pragma unroll
    for (int j = 0; j < 16; j++) o[j] = 0.f;
    for (int kk = 0; kk < 64; kk++) {
        float p = buf0[qr * 64 + kk];
#pragma unroll
        for (int j4 = 0; j4 < 4; j4++) {
            float4 vv = ((float4*)(buf1 + kk * 64 + kc0))[j4];
            o[j4 * 4 + 0] += p * vv.x;
            o[j4 * 4 + 1] += p * vv.y;
            o[j4 * 4 + 2] += p * vv.z;
            o[j4 * 4 + 3] += p * vv.w;
        }
    }
    int gt = base + qr;
    if (gt >= 0 && gt < Tt) {
        size_t ob = ((size_t)(b * Tt + gt)) * Dm + h * HDm + kc0;
#pragma unroll
        for (int j = 0; j < 16; j += 2) {
            __nv_bfloat16 h0, l0, h1, l1;
            bfsplit(o[j], h0, l0);
            bfsplit(o[j + 1], h1, l1);
            *(__nv_bfloat162*)(ahi + ob + j) = __halves2bfloat162(h0, h1);
            *(__nv_bfloat162*)(alo + ob + j) = __halves2bfloat162(l0, l1);
        }
    }
}

// ============================================================
// Host driver
// ============================================================
extern "C" void kernel_launch(void* const* d_in, const int* in_sizes, int n_in,
                              void* d_out, int out_size) {
    const int*   inputs = (const int*)  d_in[0];
    const float* embed  = (const float*)d_in[1];
    const float* wq     = (const float*)d_in[2];
    const float* wk     = (const float*)d_in[3];
    const float* wv     = (const float*)d_in[4];
    const float* wo     = (const float*)d_in[5];
    const float* ln1_s  = (const float*)d_in[6];
    const float* ln1_b  = (const float*)d_in[7];
    const float* ln2_s  = (const float*)d_in[8];
    const float* ln2_b  = (const float*)d_in[9];
    const float* w1     = (const float*)d_in[10];
    const float* b1     = (const float*)d_in[11];
    const float* w2     = (const float*)d_in[12];
    const float* b2     = (const float*)d_in[13];
    const float* lnf_s  = (const float*)d_in[14];
    const float* lnf_b  = (const float*)d_in[15];

    float *x, *qkv;
    __nv_bfloat16 *hhi, *hlo, *ahi, *alo, *mhi, *mlo, *whi, *wlo;
    cudaGetSymbolAddress((void**)&x,   g_x);
    cudaGetSymbolAddress((void**)&qkv, g_qkv);
    cudaGetSymbolAddress((void**)&hhi, g_hhi);
    cudaGetSymbolAddress((void**)&hlo, g_hlo);
    cudaGetSymbolAddress((void**)&ahi, g_ahi);
    cudaGetSymbolAddress((void**)&alo, g_alo);
    cudaGetSymbolAddress((void**)&mhi, g_mhi);
    cudaGetSymbolAddress((void**)&mlo, g_mlo);
    cudaGetSymbolAddress((void**)&whi, g_whi);
    cudaGetSymbolAddress((void**)&wlo, g_wlo);

    cudaFuncSetAttribute(hgemm<false,false,false,true,false>, cudaFuncAttributeMaxDynamicSharedMemorySize, SMEM_GEMM);
    cudaFuncSetAttribute(hgemm<true, false,false,true,false>, cudaFuncAttributeMaxDynamicSharedMemorySize, SMEM_GEMM);
    cudaFuncSetAttribute(hgemm<false,true, true, false,true>, cudaFuncAttributeMaxDynamicSharedMemorySize, SMEM_GEMM);
    cudaFuncSetAttribute(hgemm<true, false,true, true, false>, cudaFuncAttributeMaxDynamicSharedMemorySize, SMEM_GEMM);

    wprep_all<<<18432, dim3(32, 8)>>>(wq, wk, wv, wo, w1, w2, whi, wlo);
    embed_kernel<<<(TOK * Dm) / 256, 256>>>(inputs, embed, x);

    dim3 gQKV(1536 / 128, TOK / 256);
    dim3 gP(Dm / 128, TOK / 256);
    dim3 gM1(MLPD / 128, TOK / 256);

    for (int l = 0; l < Lnum; l++) {
        int lp = (l & 1) ? 32 : 0;
        int nb = (l & 1) ? (Tt + 64) / 64 : Tt / 64;

        ln_kernel<true><<<TOK, 128>>>(x, ln1_s + l * Dm, ln1_b + l * Dm,
                                      nullptr, hhi, hlo);

        hgemm<false,false,false,true,false><<<gQKV, 512, SMEM_GEMM>>>(
            hhi, hlo,
            whi + OFF_QKV + (size_t)l * SZ_QKV, wlo + OFF_QKV + (size_t)l * SZ_QKV,
            nullptr, qkv, nullptr, nullptr, 1536, Dm);

        attn_kernel<<<dim3(nb, Hh, Bb), 256>>>(qkv, inputs, ahi, alo, lp);

        hgemm<true,false,false,true,false><<<gP, 512, SMEM_GEMM>>>(
            ahi, alo,
            whi + OFF_WO + (size_t)l * WSZP, wlo + OFF_WO + (size_t)l * WSZP,
            nullptr, x, nullptr, nullptr, Dm, Dm);

        ln_kernel<true><<<TOK, 128>>>(x, ln2_s + l * Dm, ln2_b + l * Dm,
                                      nullptr, hhi, hlo);

        hgemm<false,true,true,false,true><<<gM1, 512, SMEM_GEMM>>>(
            hhi, hlo,
            whi + OFF_W1 + (size_t)l * WSZM, wlo + OFF_W1 + (size_t)l * WSZM,
            b1 + (size_t)l * MLPD, nullptr, mhi, mlo, MLPD, Dm);

        hgemm<true,false,true,true,false><<<gP, 512, SMEM_GEMM>>>(
            mhi, mlo,
            whi + OFF_W2 + (size_t)l * WSZM, wlo + OFF_W2 + (size_t)l * WSZM,
            b2 + (size_t)l * Dm, x, nullptr, nullptr, Dm, MLPD);
    }

    ln_kernel<false><<<TOK, 128>>>(x, lnf_s, lnf_b, (float*)d_out, nullptr, nullptr);
}